// round 7
// baseline (speedup 1.0000x reference)
#include <cuda_runtime.h>
#include <cuda_bf16.h>
#include <cstdint>

#define B 8192
#define D 128
#define KD 256            // hi|lo concatenated K
#define AST 264           // smem row stride in bf16 (conflict-free ldmatrix)
#define NSL 2             // j-slot split
#define JT_PER 32         // j-tiles per slot
#define TPB 256
#define FEPS 1e-5f

// ---------------- device scratch ----------------
__device__ float          g_sq[B];
__device__ float2         g_sl[B];              // (sq_j, label bits)
__device__ __nv_bfloat16  g_g2[B * KD];         // [hi(128) | lo(128)] per row
__device__ float          g_rm1[NSL * B];
__device__ float          g_rm2[NSL * B];
__device__ float          g_rmn[NSL * B];
__device__ float          g_bsum[64];

// smem byte offsets
#define SM_A   0
#define SM_B0  67584
#define SM_B1  135168
#define SM_ST  202752
#define SMEM_TOTAL 208896

__device__ __forceinline__ uint32_t s2u(const void* p) {
    uint32_t a;
    asm("{ .reg .u64 t; cvta.to.shared.u64 t, %1; cvt.u32.u64 %0, t; }" : "=r"(a) : "l"(p));
    return a;
}
__device__ __forceinline__ void cpa16(uint32_t dst, const void* src) {
    asm volatile("cp.async.cg.shared.global [%0], [%1], 16;" :: "r"(dst), "l"(src));
}
#define CP_COMMIT() asm volatile("cp.async.commit_group;" ::: "memory")
#define CP_WAIT0()  asm volatile("cp.async.wait_group 0;" ::: "memory")

__device__ __forceinline__ void ldsm4(uint32_t& r0, uint32_t& r1, uint32_t& r2,
                                      uint32_t& r3, uint32_t a) {
    asm volatile("ldmatrix.sync.aligned.m8n8.x4.shared.b16 {%0,%1,%2,%3}, [%4];"
                 : "=r"(r0), "=r"(r1), "=r"(r2), "=r"(r3) : "r"(a));
}
__device__ __forceinline__ void mma16816(float* c, const uint32_t* a, const uint32_t* b) {
    asm volatile(
        "mma.sync.aligned.m16n8k16.row.col.f32.bf16.bf16.f32 "
        "{%0,%1,%2,%3}, {%4,%5,%6,%7}, {%8,%9}, {%0,%1,%2,%3};"
        : "+f"(c[0]), "+f"(c[1]), "+f"(c[2]), "+f"(c[3])
        : "r"(a[0]), "r"(a[1]), "r"(a[2]), "r"(a[3]), "r"(b[0]), "r"(b[1]));
}

// ---------------- prepass 1: row norms + (sq,label) ----------------
__global__ void sq_sl_kernel(const float* __restrict__ F, const int* __restrict__ lab) {
    int gtid = blockIdx.x * blockDim.x + threadIdx.x;
    int row  = gtid >> 5, lane = gtid & 31;
    float4 v = reinterpret_cast<const float4*>(F)[row * (D / 4) + lane];
    float s = v.x * v.x + v.y * v.y + v.z * v.z + v.w * v.w;
    #pragma unroll
    for (int d = 16; d > 0; d >>= 1) s += __shfl_xor_sync(0xffffffffu, s, d);
    if (lane == 0) {
        g_sq[row] = s;
        g_sl[row] = make_float2(s, __int_as_float(lab[row]));
    }
}

// ---------------- prepass 2: hi/lo split to K=256 bf16 ----------------
__global__ void prep_kernel(const float* __restrict__ F) {
    int id  = blockIdx.x * blockDim.x + threadIdx.x;
    int row = id >> 5, c4 = (id & 31) << 2;
    float4 v = *reinterpret_cast<const float4*>(F + row * D + c4);
    float vv[4] = {v.x, v.y, v.z, v.w};
    unsigned short h[4], l[4];
    #pragma unroll
    for (int e = 0; e < 4; e++) {
        __nv_bfloat16 bh = __float2bfloat16(vv[e]);
        __nv_bfloat16 bl = __float2bfloat16(vv[e] - __bfloat162float(bh));
        h[e] = __bfloat16_as_ushort(bh);
        l[e] = __bfloat16_as_ushort(bl);
    }
    uint2* dst = reinterpret_cast<uint2*>(g_g2 + row * KD);
    dst[c4 >> 2]        = make_uint2((uint32_t)h[0] | ((uint32_t)h[1] << 16),
                                     (uint32_t)h[2] | ((uint32_t)h[3] << 16));
    dst[(c4 >> 2) + 32] = make_uint2((uint32_t)l[0] | ((uint32_t)l[1] << 16),
                                     (uint32_t)l[2] | ((uint32_t)l[3] << 16));
}

__device__ __forceinline__ void issue_tile(uint32_t smb, int dst_off, int r0, int tid) {
    #pragma unroll
    for (int p = 0; p < 16; p++) {
        int c   = p * TPB + tid;
        int row = c >> 5, off = c & 31;
        cpa16(smb + dst_off + row * (AST * 2) + off * 16,
              g_g2 + (r0 + row) * KD + off * 8);
    }
}

// ---------------- main HMMA + pipelined hard-mining kernel ----------------
__global__ __launch_bounds__(TPB)
void hmma_kernel(const int* __restrict__ lab) {
    extern __shared__ char smem[];
    const uint32_t smb = s2u(smem);
    const int tid  = threadIdx.x;
    const int wid  = tid >> 5, lane = tid & 31;
    const int wm   = wid >> 2, wn = wid & 3;     // warp grid 2x4, tile 64x32
    const int q    = lane >> 2, tq = lane & 3;
    const int it   = blockIdx.x, slot = blockIdx.y;
    const int i0   = it * 128;
    const float FINF = __int_as_float(0x7f800000);
    const float NINF = __int_as_float(0xff800000);

    // prologue: A tile + B tile 0
    issue_tile(smb, SM_A, i0, tid);
    issue_tile(smb, SM_B0, (slot * JT_PER) * 128, tid);
    CP_COMMIT();

    // ldmatrix per-thread addresses
    const int lrow = lane & 7, grp = lane >> 3;
    int arow[4];
    #pragma unroll
    for (int mt = 0; mt < 4; mt++)
        arow[mt] = (wm * 64 + mt * 16 + lrow + (grp & 1) * 8) * AST;
    const int acol = (grp >> 1) * 8;
    // merged B ldsm.x4: matrices (nt,klo),(nt,khi),(nt+1,klo),(nt+1,khi)
    int bb[2];
    #pragma unroll
    for (int ntp = 0; ntp < 2; ntp++)
        bb[ntp] = (wn * 32 + ntp * 16 + ((grp >> 1) & 1) * 8 + lrow) * AST
                + (grp & 1) * 8;

    int li[4][2];
    #pragma unroll
    for (int mt = 0; mt < 4; mt++) {
        li[mt][0] = lab[i0 + wm * 64 + mt * 16 + q];
        li[mt][1] = lab[i0 + wm * 64 + mt * 16 + q + 8];
    }

    float m1[8], m2[8], mn[8];
    #pragma unroll
    for (int r = 0; r < 8; r++) { m1[r] = FINF; m2[r] = FINF; mn[r] = FINF; }

    // double accumulators; accB primed to -inf so tile-0's "epilogue" is a no-op
    float accA[4][4][4], accB[4][4][4];
    #pragma unroll
    for (int mt = 0; mt < 4; mt++)
        #pragma unroll
        for (int nt = 0; nt < 4; nt++)
            #pragma unroll
            for (int e = 0; e < 4; e++) accB[mt][nt][e] = NINF;

    CP_WAIT0();
    __syncthreads();

    // one epilogue cell (4 values) of the PREVIOUS tile's acc
    auto epi_cell = [&](const float (*prv)[4][4], int j0p, int mt, int nt) {
        const int c0 = j0p + wn * 32 + nt * 8 + 2 * tq;
        float2 sl0 = g_sl[c0], sl1 = g_sl[c0 + 1];
        const int lj0 = __float_as_int(sl0.y), lj1 = __float_as_int(sl1.y);
        #pragma unroll
        for (int h = 0; h < 2; h++) {
            const int r = mt * 2 + h;
            const int lir = li[mt][h];
            float t0 = fmaf(-2.f, prv[mt][nt][2 * h],     sl0.x);
            float t1 = fmaf(-2.f, prv[mt][nt][2 * h + 1], sl1.x);
            bool s0 = (lir == lj0), s1 = (lir == lj1);
            float ts = s0 ? t0 : FINF, tn = s0 ? FINF : t0;
            m2[r] = fminf(m2[r], fmaxf(m1[r], ts));
            m1[r] = fminf(m1[r], ts);
            mn[r] = fminf(mn[r], tn);
            ts = s1 ? t1 : FINF; tn = s1 ? FINF : t1;
            m2[r] = fminf(m2[r], fmaxf(m1[r], ts));
            m1[r] = fminf(m1[r], ts);
            mn[r] = fminf(mn[r], tn);
        }
    };

    // tile body: MMA into cur (smem buf bufo), epilogue of prv spliced per k-step
    auto body = [&](float (*cur)[4][4], const float (*prv)[4][4],
                    int s, int bufo, int pref_off) {
        if (s + 1 < JT_PER) {
            issue_tile(smb, pref_off, (slot * JT_PER + s + 1) * 128, tid);
            CP_COMMIT();
        }
        const int j0p = (slot * JT_PER + (s ? s - 1 : 0)) * 128;
        #pragma unroll
        for (int mt = 0; mt < 4; mt++)
            #pragma unroll
            for (int nt = 0; nt < 4; nt++)
                #pragma unroll
                for (int e = 0; e < 4; e++) cur[mt][nt][e] = 0.f;
        #pragma unroll
        for (int ks = 0; ks < KD / 16; ks++) {
            const int k0 = ks * 16;
            uint32_t a[4][4], b[4][2];
            #pragma unroll
            for (int mt = 0; mt < 4; mt++)
                ldsm4(a[mt][0], a[mt][1], a[mt][2], a[mt][3],
                      smb + SM_A + (arow[mt] + k0 + acol) * 2);
            ldsm4(b[0][0], b[0][1], b[1][0], b[1][1],
                  smb + bufo + (bb[0] + k0) * 2);
            ldsm4(b[2][0], b[2][1], b[3][0], b[3][1],
                  smb + bufo + (bb[1] + k0) * 2);
            #pragma unroll
            for (int mt = 0; mt < 4; mt++)
                #pragma unroll
                for (int nt = 0; nt < 4; nt++)
                    mma16816(cur[mt][nt], a[mt], b[nt]);
            // epilogue chunk of previous tile: cell (ks&3, ks>>2)
            epi_cell(prv, j0p, ks & 3, ks >> 2);
        }
        if (s + 1 < JT_PER) CP_WAIT0();
        __syncthreads();
    };

    #pragma unroll 1
    for (int s = 0; s < JT_PER; s += 2) {
        body(accA, accB, s,     SM_B0, SM_B1);   // even tile -> accA, epi accB
        body(accB, accA, s + 1, SM_B1, SM_B0);   // odd tile  -> accB, epi accA
    }
    // final epilogue: tile JT_PER-1 lives in accB
    {
        const int j0p = (slot * JT_PER + JT_PER - 1) * 128;
        #pragma unroll
        for (int cell = 0; cell < 16; cell++)
            epi_cell(accB, j0p, cell & 3, cell >> 2);
    }

    // quad reduce (lanes sharing rows: xor over tq bits)
    #pragma unroll
    for (int d = 1; d < 4; d <<= 1) {
        #pragma unroll
        for (int r = 0; r < 8; r++) {
            float o1 = __shfl_xor_sync(0xffffffffu, m1[r], d);
            float o2 = __shfl_xor_sync(0xffffffffu, m2[r], d);
            float on = __shfl_xor_sync(0xffffffffu, mn[r], d);
            m2[r] = fminf(fminf(m2[r], o2), fmaxf(m1[r], o1));
            m1[r] = fminf(m1[r], o1);
            mn[r] = fminf(mn[r], on);
        }
    }
    float* st = reinterpret_cast<float*>(smem + SM_ST);   // [4][3][128]
    if (tq == 0) {
        #pragma unroll
        for (int mt = 0; mt < 4; mt++)
            #pragma unroll
            for (int h = 0; h < 2; h++) {
                int r = wm * 64 + mt * 16 + q + 8 * h;
                st[wn * 384 + 0 * 128 + r] = m1[mt * 2 + h];
                st[wn * 384 + 1 * 128 + r] = m2[mt * 2 + h];
                st[wn * 384 + 2 * 128 + r] = mn[mt * 2 + h];
            }
    }
    __syncthreads();
    if (tid < 128) {
        float a1 = FINF, a2 = FINF, an = FINF;
        #pragma unroll
        for (int w = 0; w < 4; w++) {
            float b1 = st[w * 384 + tid], b2 = st[w * 384 + 128 + tid],
                  bn = st[w * 384 + 256 + tid];
            a2 = fminf(fminf(a2, b2), fmaxf(a1, b1));
            a1 = fminf(a1, b1);
            an = fminf(an, bn);
        }
        g_rm1[slot * B + i0 + tid] = a1;
        g_rm2[slot * B + i0 + tid] = a2;
        g_rmn[slot * B + i0 + tid] = an;
    }
}

// ---------------- merge partials + hinge + block sums ----------------
__global__ void merge1_kernel() {
    const int tid = threadIdx.x;
    const int row = blockIdx.x * 128 + tid;
    const float FINF = __int_as_float(0x7f800000);
    __shared__ float red[128];
    float a1 = FINF, a2 = FINF, an = FINF;
    #pragma unroll
    for (int s = 0; s < NSL; s++) {
        float b1 = g_rm1[s * B + row], b2 = g_rm2[s * B + row], bn = g_rmn[s * B + row];
        a2 = fminf(fminf(a2, b2), fmaxf(a1, b1));
        a1 = fminf(a1, b1);
        an = fminf(an, bn);
    }
    float sqi = g_sq[row];
    float pos = sqrtf(fmaxf(sqi + a2 + FEPS, 0.f));
    float neg = sqrtf(fmaxf(sqi + an + FEPS, 0.f));
    red[tid] = fmaxf(1.0f + pos - neg, 0.f);
    __syncthreads();
    for (int s = 64; s > 0; s >>= 1) {
        if (tid < s) red[tid] += red[tid + s];
        __syncthreads();
    }
    if (tid == 0) g_bsum[blockIdx.x] = red[0];
}

__global__ void merge2_kernel(float* __restrict__ out) {
    int tid = threadIdx.x;   // 32
    float s = g_bsum[tid] + g_bsum[tid + 32];
    #pragma unroll
    for (int d = 16; d > 0; d >>= 1) s += __shfl_xor_sync(0xffffffffu, s, d);
    if (tid == 0) out[0] = s * (1.0f / (float)B);
}

extern "C" void kernel_launch(void* const* d_in, const int* in_sizes, int n_in,
                              void* d_out, int out_size) {
    (void)in_sizes; (void)n_in; (void)out_size;
    const float* F   = (const float*)d_in[0];
    const int*   lab = (const int*)d_in[1];
    float*       out = (float*)d_out;

    cudaFuncSetAttribute(hmma_kernel,
                         cudaFuncAttributeMaxDynamicSharedMemorySize, SMEM_TOTAL);

    sq_sl_kernel<<<B / 8, TPB>>>(F, lab);
    prep_kernel<<<B * 32 / TPB, TPB>>>(F);
    dim3 grid(64, NSL);
    hmma_kernel<<<grid, TPB, SMEM_TOTAL>>>(lab);
    merge1_kernel<<<64, 128>>>();
    merge2_kernel<<<1, 32>>>(out);
}

// round 8
// speedup vs baseline: 2.0886x; 2.0886x over previous
#include <cuda_runtime.h>
#include <cuda_bf16.h>
#include <cstdint>

#define B 8192
#define D 128
#define KD 128            // bf16 hi only (cross-term error dominates either way)
#define AST 136           // smem row stride in bf16 (272B, conflict-free ldmatrix)
#define NSL 2             // j-slot split
#define JT_PER 32         // j-tiles per slot
#define TPB 256
#define FEPS 1e-5f

// ---------------- device scratch ----------------
__device__ float  g_sq[B];
__device__ float2 g_sl[B];            // (sq_j, label bits)
__device__ uint2  g_hi[B * 32];       // bf16 rows, 8B chunks ([B][D] bf16 = 2MB)
__device__ float  g_rm1[NSL * B];
__device__ float  g_rm2[NSL * B];
__device__ float  g_rmn[NSL * B];
__device__ float  g_bsum[64];

// smem byte offsets
#define SM_A   0
#define SM_B0  34816
#define SM_B1  69632
#define SM_ST  104448                  // staging float[4][3][128] = 6144B
#define SMEM_TOTAL 110592

__device__ __forceinline__ uint32_t s2u(const void* p) {
    uint32_t a;
    asm("{ .reg .u64 t; cvta.to.shared.u64 t, %1; cvt.u32.u64 %0, t; }" : "=r"(a) : "l"(p));
    return a;
}
__device__ __forceinline__ void cpa16(uint32_t dst, const void* src) {
    asm volatile("cp.async.cg.shared.global [%0], [%1], 16;" :: "r"(dst), "l"(src));
}
#define CP_COMMIT() asm volatile("cp.async.commit_group;" ::: "memory")
#define CP_WAIT0()  asm volatile("cp.async.wait_group 0;" ::: "memory")

__device__ __forceinline__ void ldsm4(uint32_t& r0, uint32_t& r1, uint32_t& r2,
                                      uint32_t& r3, uint32_t a) {
    asm volatile("ldmatrix.sync.aligned.m8n8.x4.shared.b16 {%0,%1,%2,%3}, [%4];"
                 : "=r"(r0), "=r"(r1), "=r"(r2), "=r"(r3) : "r"(a));
}
__device__ __forceinline__ void mma16816(float* c, const uint32_t* a, const uint32_t* b) {
    asm volatile(
        "mma.sync.aligned.m16n8k16.row.col.f32.bf16.bf16.f32 "
        "{%0,%1,%2,%3}, {%4,%5,%6,%7}, {%8,%9}, {%0,%1,%2,%3};"
        : "+f"(c[0]), "+f"(c[1]), "+f"(c[2]), "+f"(c[3])
        : "r"(a[0]), "r"(a[1]), "r"(a[2]), "r"(a[3]), "r"(b[0]), "r"(b[1]));
}

// ---------------- single prepass: bf16 convert + row norms + (sq,label) ----------------
__global__ void prep_kernel(const float* __restrict__ F, const int* __restrict__ lab) {
    int gtid = blockIdx.x * blockDim.x + threadIdx.x;
    int row  = gtid >> 5, lane = gtid & 31;
    float4 v = reinterpret_cast<const float4*>(F)[row * 32 + lane];
    unsigned short h[4];
    h[0] = __bfloat16_as_ushort(__float2bfloat16(v.x));
    h[1] = __bfloat16_as_ushort(__float2bfloat16(v.y));
    h[2] = __bfloat16_as_ushort(__float2bfloat16(v.z));
    h[3] = __bfloat16_as_ushort(__float2bfloat16(v.w));
    g_hi[row * 32 + lane] = make_uint2((uint32_t)h[0] | ((uint32_t)h[1] << 16),
                                       (uint32_t)h[2] | ((uint32_t)h[3] << 16));
    float s = v.x * v.x + v.y * v.y + v.z * v.z + v.w * v.w;
    #pragma unroll
    for (int d = 16; d > 0; d >>= 1) s += __shfl_xor_sync(0xffffffffu, s, d);
    if (lane == 0) {
        g_sq[row] = s;
        g_sl[row] = make_float2(s, __int_as_float(lab[row]));
    }
}

// copy a 128-row x 128-col bf16 tile (gmem row r0) into smem (AST-padded rows)
__device__ __forceinline__ void issue_tile(uint32_t smb, int dst_off, int r0, int tid) {
    const char* base = reinterpret_cast<const char*>(g_hi);
    #pragma unroll
    for (int p = 0; p < 8; p++) {
        int c   = p * TPB + tid;                 // 0..2047 (16B chunks)
        int row = c >> 4, off = c & 15;
        cpa16(smb + dst_off + row * (AST * 2) + off * 16,
              base + (r0 + row) * 256 + off * 16);
    }
}

// ---------------- main HMMA + hard-mining kernel ----------------
__global__ __launch_bounds__(TPB)
void hmma_kernel(const int* __restrict__ lab) {
    extern __shared__ char smem[];
    const uint32_t smb = s2u(smem);
    const int tid  = threadIdx.x;
    const int wid  = tid >> 5, lane = tid & 31;
    const int wm   = wid >> 2, wn = wid & 3;     // warp grid 2x4, tile 64x32
    const int q    = lane >> 2, tq = lane & 3;
    const int it   = blockIdx.x, slot = blockIdx.y;
    const int i0   = it * 128;
    const float FINF = __int_as_float(0x7f800000);

    // prologue: A tile + B tile 0
    issue_tile(smb, SM_A, i0, tid);
    issue_tile(smb, SM_B0, (slot * JT_PER) * 128, tid);
    CP_COMMIT();

    // ldmatrix per-thread addresses
    const int lrow = lane & 7, grp = lane >> 3;
    int arow[4];
    #pragma unroll
    for (int mt = 0; mt < 4; mt++)
        arow[mt] = (wm * 64 + mt * 16 + lrow + (grp & 1) * 8) * AST;
    const int acol = (grp >> 1) * 8;
    // merged B ldsm.x4: matrices (nt,klo),(nt,khi),(nt+1,klo),(nt+1,khi)
    int bb[2];
    #pragma unroll
    for (int ntp = 0; ntp < 2; ntp++)
        bb[ntp] = (wn * 32 + ntp * 16 + ((grp >> 1) & 1) * 8 + lrow) * AST
                + (grp & 1) * 8;

    int li[4][2];
    #pragma unroll
    for (int mt = 0; mt < 4; mt++) {
        li[mt][0] = lab[i0 + wm * 64 + mt * 16 + q];
        li[mt][1] = lab[i0 + wm * 64 + mt * 16 + q + 8];
    }

    float m1[8], m2[8], mn[8];
    #pragma unroll
    for (int r = 0; r < 8; r++) { m1[r] = FINF; m2[r] = FINF; mn[r] = FINF; }

    CP_WAIT0();
    __syncthreads();

    for (int s = 0; s < JT_PER; s++) {
        const int bufo = (s & 1) ? SM_B1 : SM_B0;
        if (s + 1 < JT_PER) {
            issue_tile(smb, (s & 1) ? SM_B0 : SM_B1,
                       (slot * JT_PER + s + 1) * 128, tid);
            CP_COMMIT();
        }

        float acc[4][4][4];
        #pragma unroll
        for (int mt = 0; mt < 4; mt++)
            #pragma unroll
            for (int nt = 0; nt < 4; nt++)
                #pragma unroll
                for (int e = 0; e < 4; e++) acc[mt][nt][e] = 0.f;

        #pragma unroll
        for (int ks = 0; ks < KD / 16; ks++) {
            const int k0 = ks * 16;
            uint32_t a[4][4], b[4][2];
            #pragma unroll
            for (int mt = 0; mt < 4; mt++)
                ldsm4(a[mt][0], a[mt][1], a[mt][2], a[mt][3],
                      smb + SM_A + (arow[mt] + k0 + acol) * 2);
            ldsm4(b[0][0], b[0][1], b[1][0], b[1][1],
                  smb + bufo + (bb[0] + k0) * 2);
            ldsm4(b[2][0], b[2][1], b[3][0], b[3][1],
                  smb + bufo + (bb[1] + k0) * 2);
            #pragma unroll
            for (int mt = 0; mt < 4; mt++)
                #pragma unroll
                for (int nt = 0; nt < 4; nt++)
                    mma16816(acc[mt][nt], a[mt], b[nt]);
        }

        // epilogue on register accumulators
        const int j0 = (slot * JT_PER + s) * 128;
        #pragma unroll
        for (int nt = 0; nt < 4; nt++) {
            const int c0 = j0 + wn * 32 + nt * 8 + 2 * tq;
            float2 sl0 = g_sl[c0], sl1 = g_sl[c0 + 1];
            const int lj0 = __float_as_int(sl0.y), lj1 = __float_as_int(sl1.y);
            #pragma unroll
            for (int mt = 0; mt < 4; mt++) {
                #pragma unroll
                for (int h = 0; h < 2; h++) {
                    const int r = mt * 2 + h;
                    const int lir = li[mt][h];
                    float t0 = fmaf(-2.f, acc[mt][nt][2 * h],     sl0.x);
                    float t1 = fmaf(-2.f, acc[mt][nt][2 * h + 1], sl1.x);
                    bool s0 = (lir == lj0), s1 = (lir == lj1);
                    float ts = s0 ? t0 : FINF, tn = s0 ? FINF : t0;
                    m2[r] = fminf(m2[r], fmaxf(m1[r], ts));
                    m1[r] = fminf(m1[r], ts);
                    mn[r] = fminf(mn[r], tn);
                    ts = s1 ? t1 : FINF; tn = s1 ? FINF : t1;
                    m2[r] = fminf(m2[r], fmaxf(m1[r], ts));
                    m1[r] = fminf(m1[r], ts);
                    mn[r] = fminf(mn[r], tn);
                }
            }
        }

        if (s + 1 < JT_PER) CP_WAIT0();
        __syncthreads();
    }

    // quad reduce (lanes sharing rows: xor over tq bits)
    #pragma unroll
    for (int d = 1; d < 4; d <<= 1) {
        #pragma unroll
        for (int r = 0; r < 8; r++) {
            float o1 = __shfl_xor_sync(0xffffffffu, m1[r], d);
            float o2 = __shfl_xor_sync(0xffffffffu, m2[r], d);
            float on = __shfl_xor_sync(0xffffffffu, mn[r], d);
            m2[r] = fminf(fminf(m2[r], o2), fmaxf(m1[r], o1));
            m1[r] = fminf(m1[r], o1);
            mn[r] = fminf(mn[r], on);
        }
    }
    float* st = reinterpret_cast<float*>(smem + SM_ST);   // [4][3][128]
    if (tq == 0) {
        #pragma unroll
        for (int mt = 0; mt < 4; mt++)
            #pragma unroll
            for (int h = 0; h < 2; h++) {
                int r = wm * 64 + mt * 16 + q + 8 * h;
                st[wn * 384 + 0 * 128 + r] = m1[mt * 2 + h];
                st[wn * 384 + 1 * 128 + r] = m2[mt * 2 + h];
                st[wn * 384 + 2 * 128 + r] = mn[mt * 2 + h];
            }
    }
    __syncthreads();
    if (tid < 128) {
        float a1 = FINF, a2 = FINF, an = FINF;
        #pragma unroll
        for (int w = 0; w < 4; w++) {
            float b1 = st[w * 384 + tid], b2 = st[w * 384 + 128 + tid],
                  bn = st[w * 384 + 256 + tid];
            a2 = fminf(fminf(a2, b2), fmaxf(a1, b1));
            a1 = fminf(a1, b1);
            an = fminf(an, bn);
        }
        g_rm1[slot * B + i0 + tid] = a1;
        g_rm2[slot * B + i0 + tid] = a2;
        g_rmn[slot * B + i0 + tid] = an;
    }
}

// ---------------- merge partials + hinge + block sums ----------------
__global__ void merge1_kernel() {
    const int tid = threadIdx.x;
    const int row = blockIdx.x * 128 + tid;
    const float FINF = __int_as_float(0x7f800000);
    __shared__ float red[128];
    float a1 = FINF, a2 = FINF, an = FINF;
    #pragma unroll
    for (int s = 0; s < NSL; s++) {
        float b1 = g_rm1[s * B + row], b2 = g_rm2[s * B + row], bn = g_rmn[s * B + row];
        a2 = fminf(fminf(a2, b2), fmaxf(a1, b1));
        a1 = fminf(a1, b1);
        an = fminf(an, bn);
    }
    float sqi = g_sq[row];
    float pos = sqrtf(fmaxf(sqi + a2 + FEPS, 0.f));
    float neg = sqrtf(fmaxf(sqi + an + FEPS, 0.f));
    red[tid] = fmaxf(1.0f + pos - neg, 0.f);
    __syncthreads();
    for (int s = 64; s > 0; s >>= 1) {
        if (tid < s) red[tid] += red[tid + s];
        __syncthreads();
    }
    if (tid == 0) g_bsum[blockIdx.x] = red[0];
}

__global__ void merge2_kernel(float* __restrict__ out) {
    int tid = threadIdx.x;   // 32
    float s = g_bsum[tid] + g_bsum[tid + 32];
    #pragma unroll
    for (int d = 16; d > 0; d >>= 1) s += __shfl_xor_sync(0xffffffffu, s, d);
    if (tid == 0) out[0] = s * (1.0f / (float)B);
}

extern "C" void kernel_launch(void* const* d_in, const int* in_sizes, int n_in,
                              void* d_out, int out_size) {
    (void)in_sizes; (void)n_in; (void)out_size;
    const float* F   = (const float*)d_in[0];
    const int*   lab = (const int*)d_in[1];
    float*       out = (float*)d_out;

    cudaFuncSetAttribute(hmma_kernel,
                         cudaFuncAttributeMaxDynamicSharedMemorySize, SMEM_TOTAL);

    prep_kernel<<<B / 8, TPB>>>(F, lab);
    dim3 grid(64, NSL);
    hmma_kernel<<<grid, TPB, SMEM_TOTAL>>>(lab);
    merge1_kernel<<<64, 128>>>();
    merge2_kernel<<<1, 32>>>(out);
}